// round 16
// baseline (speedup 1.0000x reference)
#include <cuda_runtime.h>
#include <cuda_fp16.h>
#include <cstdint>

#define NB 4096
#define INF 1024
#define OUTF 1024
#define NH 16
#define NM 4096
#define ND 64

// Scratch (device globals: allocation-free rule). All fp16-pair packed (u32).
__device__ uint32_t g_xh[NB * INF / 2];
__device__ uint32_t g_wh[OUTF * INF / 2];
__device__ uint32_t g_qh[NB * OUTF / 2];     // q-normalized * log2(e), fp16
__device__ uint32_t g_mh[NH * NM * ND / 2];  // normalized memories (K), fp16

// ===========================================================================
// helpers
// ===========================================================================
__device__ __forceinline__ uint32_t smem_u32(const void* p) {
    uint32_t a;
    asm("{ .reg .u64 t; cvta.to.shared.u64 t, %1; cvt.u32.u64 %0, t; }"
        : "=r"(a) : "l"(p));
    return a;
}
__device__ __forceinline__ uint32_t pack_h2(float lo, float hi) {
    uint32_t r;
    asm("cvt.rn.f16x2.f32 %0, %1, %2;" : "=r"(r) : "f"(hi), "f"(lo));
    return r;
}
__device__ __forceinline__ uint32_t ex2h2(uint32_t x) {
    uint32_t r;
    asm("ex2.approx.f16x2 %0, %1;" : "=r"(r) : "r"(x));
    return r;
}
__device__ __forceinline__ float h2sum(uint32_t w) {
    __half2 h = *reinterpret_cast<__half2*>(&w);
    float2 f = __half22float2(h);
    return f.x + f.y;
}
__device__ __forceinline__ void mma_f16(float* d, uint32_t a0, uint32_t a1,
                                        uint32_t a2, uint32_t a3,
                                        uint32_t b0, uint32_t b1) {
    asm volatile(
        "mma.sync.aligned.m16n8k16.row.col.f32.f16.f16.f32 "
        "{%0,%1,%2,%3},{%4,%5,%6,%7},{%8,%9},{%0,%1,%2,%3};"
        : "+f"(d[0]), "+f"(d[1]), "+f"(d[2]), "+f"(d[3])
        : "r"(a0), "r"(a1), "r"(a2), "r"(a3), "r"(b0), "r"(b1));
}
__device__ __forceinline__ void ldmat_x4(uint32_t& r0, uint32_t& r1,
                                         uint32_t& r2, uint32_t& r3,
                                         uint32_t addr) {
    asm volatile("ldmatrix.sync.aligned.m8n8.x4.shared.b16 {%0,%1,%2,%3}, [%4];"
                 : "=r"(r0), "=r"(r1), "=r"(r2), "=r"(r3) : "r"(addr));
}
__device__ __forceinline__ void ldmat_x4_t(uint32_t& r0, uint32_t& r1,
                                           uint32_t& r2, uint32_t& r3,
                                           uint32_t addr) {
    asm volatile(
        "ldmatrix.sync.aligned.m8n8.x4.trans.shared.b16 {%0,%1,%2,%3}, [%4];"
        : "=r"(r0), "=r"(r1), "=r"(r2), "=r"(r3) : "r"(addr));
}
__device__ __forceinline__ void cpasync16(uint32_t dst, const void* src) {
    asm volatile("cp.async.cg.shared.global [%0], [%1], 16;"
                 :: "r"(dst), "l"(src) : "memory");
}
__device__ __forceinline__ void cp_commit() {
    asm volatile("cp.async.commit_group;" ::: "memory");
}

// ===========================================================================
// Pack f32 -> fp16 pairs
// ===========================================================================
__global__ __launch_bounds__(256) void cvt_pack(const float4* __restrict__ src,
                                                uint2* __restrict__ dst, int n4) {
    int i = blockIdx.x * 256 + threadIdx.x;
    if (i < n4) {
        float4 v = src[i];
        uint2 o;
        o.x = pack_h2(v.x, v.y);
        o.y = pack_h2(v.z, v.w);
        dst[i] = o;
    }
}

// ===========================================================================
// Row L2-normalize memories, 64-elem rows -> fp16 pairs
// ===========================================================================
__global__ __launch_bounds__(256) void rownorm64_h(const float* __restrict__ src,
                                                   uint32_t* __restrict__ dst) {
    int row = blockIdx.x * 8 + (threadIdx.x >> 5);
    int lane = threadIdx.x & 31;
    float2 v = *(const float2*)(src + (size_t)row * 64 + lane * 2);
    float ss = fmaf(v.x, v.x, v.y * v.y);
#pragma unroll
    for (int o = 16; o > 0; o >>= 1) ss += __shfl_xor_sync(0xffffffffu, ss, o);
    float r = rsqrtf(ss);
    dst[(size_t)row * 32 + lane] = pack_h2(v.x * r, v.y * r);
}

// ===========================================================================
// q-GEMM (fp16): qh = rownorm64(x @ W^T) * log2(e) -> fp16 pairs.
// 128x128 tile, BK=32, FOUR-stage cp.async (3-iteration latency cover),
// 256 thr, warp tile 32x64, fused per-head L2 norm.
// ===========================================================================
#define QGS 20
#define QG_TILE (128 * QGS)
#define QG_WOFF (4 * QG_TILE)
#define QG_SMEM (8 * QG_TILE * 4)

__global__ __launch_bounds__(256, 2) void qgemm_h(const uint32_t* __restrict__ Xh,
                                                  const uint32_t* __restrict__ Wh,
                                                  uint32_t* __restrict__ Qh) {
    extern __shared__ uint32_t qsm[];
    uint32_t smb = smem_u32(qsm);

    int tid = threadIdx.x;
    int lane = tid & 31, w = tid >> 5;
    int g = lane >> 2, la3 = lane & 3;
    int wm = (w & 3) * 32, wn = (w >> 2) * 64;
    int m0 = blockIdx.y * 128, n0 = blockIdx.x * 128;

    float acc[2][8][4];
#pragma unroll
    for (int mt = 0; mt < 2; mt++)
#pragma unroll
        for (int nt = 0; nt < 8; nt++)
#pragma unroll
            for (int e = 0; e < 4; e++) acc[mt][nt][e] = 0.f;

    int sr = tid >> 1, sc = (tid & 1) * 8;
#define QGH_STAGE(kt, sl)                                                      \
    do {                                                                       \
        _Pragma("unroll")                                                      \
        for (int v = 0; v < 2; v++) {                                          \
            cpasync16(smb + (uint32_t)((sl) * QG_TILE + sr * QGS + sc + 4 * v) * 4, \
                      Xh + (size_t)(m0 + sr) * (INF / 2) + (kt) * 16 + sc + 4 * v); \
            cpasync16(smb + (uint32_t)(QG_WOFF + (sl) * QG_TILE + sr * QGS + sc + 4 * v) * 4, \
                      Wh + (size_t)(n0 + sr) * (INF / 2) + (kt) * 16 + sc + 4 * v); \
        }                                                                      \
    } while (0)

    QGH_STAGE(0, 0); cp_commit();
    QGH_STAGE(1, 1); cp_commit();
    QGH_STAGE(2, 2); cp_commit();

    for (int kt = 0; kt < 32; kt++) {
        if (kt < 30)       asm volatile("cp.async.wait_group 2;" ::: "memory");
        else if (kt == 30) asm volatile("cp.async.wait_group 1;" ::: "memory");
        else               asm volatile("cp.async.wait_group 0;" ::: "memory");
        __syncthreads();
        if (kt + 3 < 32) { QGH_STAGE(kt + 3, (kt + 3) & 3); cp_commit(); }

        const uint32_t* Xs = qsm + (kt & 3) * QG_TILE;
        const uint32_t* Ws = qsm + QG_WOFF + (kt & 3) * QG_TILE;

#pragma unroll
        for (int s = 0; s < 2; s++) {
            uint32_t af[2][4];
#pragma unroll
            for (int mt = 0; mt < 2; mt++) {
                int rr = wm + mt * 16 + g;
                af[mt][0] = Xs[rr * QGS + 8 * s + la3];
                af[mt][1] = Xs[(rr + 8) * QGS + 8 * s + la3];
                af[mt][2] = Xs[rr * QGS + 8 * s + la3 + 4];
                af[mt][3] = Xs[(rr + 8) * QGS + 8 * s + la3 + 4];
            }
#pragma unroll
            for (int nt = 0; nt < 8; nt++) {
                int nr = wn + nt * 8 + g;
                uint32_t b0 = Ws[nr * QGS + 8 * s + la3];
                uint32_t b1 = Ws[nr * QGS + 8 * s + la3 + 4];
                mma_f16(acc[0][nt], af[0][0], af[0][1], af[0][2], af[0][3], b0, b1);
                mma_f16(acc[1][nt], af[1][0], af[1][1], af[1][2], af[1][3], b0, b1);
            }
        }
    }

    // fused per-head (64-col) L2 norm epilogue, scaled by log2(e); fp16 out
#pragma unroll
    for (int mt = 0; mt < 2; mt++) {
        float sq0 = 0.f, sq1 = 0.f;
#pragma unroll
        for (int nt = 0; nt < 8; nt++) {
            sq0 = fmaf(acc[mt][nt][0], acc[mt][nt][0], sq0);
            sq0 = fmaf(acc[mt][nt][1], acc[mt][nt][1], sq0);
            sq1 = fmaf(acc[mt][nt][2], acc[mt][nt][2], sq1);
            sq1 = fmaf(acc[mt][nt][3], acc[mt][nt][3], sq1);
        }
        sq0 += __shfl_xor_sync(0xffffffffu, sq0, 1);
        sq0 += __shfl_xor_sync(0xffffffffu, sq0, 2);
        sq1 += __shfl_xor_sync(0xffffffffu, sq1, 1);
        sq1 += __shfl_xor_sync(0xffffffffu, sq1, 2);
        float r0 = rsqrtf(sq0) * 1.44269504f;
        float r1 = rsqrtf(sq1) * 1.44269504f;
        int rlo = m0 + wm + mt * 16 + g;
#pragma unroll
        for (int nt = 0; nt < 8; nt++) {
            int colw = (n0 + wn + nt * 8) / 2 + la3;
            Qh[(size_t)rlo * (OUTF / 2) + colw] =
                pack_h2(acc[mt][nt][0] * r0, acc[mt][nt][1] * r0);
            Qh[(size_t)(rlo + 8) * (OUTF / 2) + colw] =
                pack_h2(acc[mt][nt][2] * r1, acc[mt][nt][3] * r1);
        }
    }
}

// ===========================================================================
// Attention, all fp16. CTA = (head, 256 q rows), 8 warps x 32 rows (2 m16).
// Tensor pipe is the bottleneck (~533 TF/s legacy HMMA): row sums moved OFF
// the tensor pipe (f32 unpack+add of the quantized P words) — saves 8 of the
// 136 MMAs per warp-tile. Everything else as R13/R15 (pipelined ldmatrix).
// smem (u32 words): K[3][64*36] | Qstage[256*36]   (64.5 KB)
// ===========================================================================
#define KS 36
#define KTW (64 * KS)
#define QST_OFF (3 * KTW)
#define QS 36
#define AT_SMEM ((QST_OFF + 256 * QS) * 4)
#define NTILES (NM / 64)

__global__ __launch_bounds__(256, 1) void attn_h(const uint32_t* __restrict__ Qh,
                                                 const uint32_t* __restrict__ Mh,
                                                 float* __restrict__ Out) {
    extern __shared__ uint32_t smu[];
    uint32_t smb = smem_u32(smu);

    int tid = threadIdx.x;
    int lane = tid & 31, w = tid >> 5;
    int g = lane >> 2, la3 = lane & 3;
    int h = blockIdx.y;
    int q0 = blockIdx.x * 256;
    const uint32_t* mhw = Mh + (size_t)h * NM * (ND / 2);

    // ---- Q stage (cp.async group): 256 rows x 32 words ----
    {
        const uint32_t* qp = Qh + (size_t)(q0 + tid) * (OUTF / 2) + h * 32;
#pragma unroll
        for (int u = 0; u < 8; u++)
            cpasync16(smb + (uint32_t)(QST_OFF + tid * QS + u * 4) * 4, qp + u * 4);
        cp_commit();
    }

#define ATH_STAGE(tt, sl)                                                      \
    do {                                                                       \
        _Pragma("unroll")                                                      \
        for (int u = 0; u < 2; u++) {                                          \
            int chunk = tid + 256 * u;                                         \
            int r = chunk >> 3, cq = (chunk & 7) * 4;                          \
            cpasync16(smb + (uint32_t)((sl) * KTW + r * KS + cq) * 4,          \
                      mhw + (size_t)((tt) * 64 + r) * 32 + cq);                \
        }                                                                      \
    } while (0)

    ATH_STAGE(0, 0); cp_commit();
    ATH_STAGE(1, 1); cp_commit();

    asm volatile("cp.async.wait_group 2;" ::: "memory");  // Q complete
    __syncthreads();

    // ---- persistent Q a-frags (fp16: 4 k16 slices, 2 m16 tiles) ----
    int wr = w * 32;
    uint32_t qf[2][4][4];
    {
        const uint32_t* qb = smu + QST_OFF;
#pragma unroll
        for (int mt = 0; mt < 2; mt++)
#pragma unroll
            for (int s = 0; s < 4; s++) {
                int rr = wr + mt * 16 + g;
                qf[mt][s][0] = qb[rr * QS + 8 * s + la3];
                qf[mt][s][1] = qb[(rr + 8) * QS + 8 * s + la3];
                qf[mt][s][2] = qb[rr * QS + 8 * s + la3 + 4];
                qf[mt][s][3] = qb[(rr + 8) * QS + 8 * s + la3 + 4];
            }
    }

    // ---- GEMM1 non-trans ldmatrix per-lane offset ----
    int kgr = lane >> 3, ki = lane & 7;
    uint32_t koff =
        (uint32_t)(((kgr >> 1) * 8 + ki) * KS + (kgr & 1) * 4) * 4;

    // ---- GEMM2 trans-ldmatrix per-lane offset ----
    int vrow = ((lane >> 3) & 1) * 8 + (lane & 7);
    int vcolw = (lane >> 4) * 4;
    uint32_t voff = (uint32_t)(vrow * KS + vcolw) * 4;

    float oacc[2][8][4];
#pragma unroll
    for (int mt = 0; mt < 2; mt++)
#pragma unroll
        for (int nt = 0; nt < 8; nt++)
#pragma unroll
            for (int e = 0; e < 4; e++) oacc[mt][nt][e] = 0.f;
    float psum[2][2] = {{0.f, 0.f}, {0.f, 0.f}};

    for (int t = 0; t < NTILES; t++) {
        if (t < NTILES - 1) asm volatile("cp.async.wait_group 1;" ::: "memory");
        else                asm volatile("cp.async.wait_group 0;" ::: "memory");
        __syncthreads();  // K(t) visible; all warps done with slot (t-1)%3

        // stage t+2 into slot (t+2)%3 = (t-1)%3 (freed by the sync above)
        if (t + 2 < NTILES) { ATH_STAGE(t + 2, (t + 2) % 3); cp_commit(); }

        uint32_t slotb = smb + (uint32_t)((t % 3) * KTW) * 4;
        uint32_t kbase = slotb + koff;
        uint32_t vbase = slotb + voff;

        // ---- GEMM1: S = Q K^T, B loads pipelined one step ahead ----
        float sacc[2][8][4];
#pragma unroll
        for (int mt = 0; mt < 2; mt++)
#pragma unroll
            for (int nt = 0; nt < 8; nt++)
#pragma unroll
                for (int e = 0; e < 4; e++) sacc[mt][nt][e] = 0.f;

        {
            uint32_t cb[4];  // current b-frags
            ldmat_x4(cb[0], cb[1], cb[2], cb[3], kbase);  // (s=0,j=0)
#pragma unroll
            for (int it = 0; it < 16; it++) {
                int s = it >> 2, j = it & 3;
                uint32_t nb[4];
                if (it < 15) {
                    int n_it = it + 1;
                    int ns = n_it >> 2, nj = n_it & 3;
                    ldmat_x4(nb[0], nb[1], nb[2], nb[3],
                             kbase + (uint32_t)((16 * nj * KS + 8 * ns) * 4));
                }
                mma_f16(sacc[0][2 * j], qf[0][s][0], qf[0][s][1], qf[0][s][2],
                        qf[0][s][3], cb[0], cb[1]);
                mma_f16(sacc[1][2 * j], qf[1][s][0], qf[1][s][1], qf[1][s][2],
                        qf[1][s][3], cb[0], cb[1]);
                mma_f16(sacc[0][2 * j + 1], qf[0][s][0], qf[0][s][1],
                        qf[0][s][2], qf[0][s][3], cb[2], cb[3]);
                mma_f16(sacc[1][2 * j + 1], qf[1][s][0], qf[1][s][1],
                        qf[1][s][2], qf[1][s][3], cb[2], cb[3]);
                cb[0] = nb[0]; cb[1] = nb[1]; cb[2] = nb[2]; cb[3] = nb[3];
            }
        }

        // ---- P = 2^S (ex2.f16x2) + f32 row sums from the quantized P ----
        uint32_t pf[2][8][2];
#pragma unroll
        for (int mt = 0; mt < 2; mt++)
#pragma unroll
            for (int nt = 0; nt < 8; nt++) {
                uint32_t p0 = ex2h2(pack_h2(sacc[mt][nt][0], sacc[mt][nt][1]));
                uint32_t p1 = ex2h2(pack_h2(sacc[mt][nt][2], sacc[mt][nt][3]));
                pf[mt][nt][0] = p0;
                pf[mt][nt][1] = p1;
                psum[mt][0] += h2sum(p0);
                psum[mt][1] += h2sum(p1);
            }

        // ---- GEMM2: O += P V, B loads pipelined one step ahead ----
        {
            uint32_t cb[4];
            ldmat_x4_t(cb[0], cb[1], cb[2], cb[3], vbase);  // (s2=0,np=0)
#pragma unroll
            for (int it = 0; it < 16; it++) {
                int s2 = it >> 2, np = it & 3;
                uint32_t nb[4];
                if (it < 15) {
                    int n_it = it + 1;
                    int ns2 = n_it >> 2, nnp = n_it & 3;
                    ldmat_x4_t(nb[0], nb[1], nb[2], nb[3],
                               vbase + (uint32_t)(16 * ns2 * KS) * 4 +
                                   (uint32_t)(nnp * 32));
                }
                mma_f16(oacc[0][2 * np],
                        pf[0][2 * s2][0], pf[0][2 * s2][1],
                        pf[0][2 * s2 + 1][0], pf[0][2 * s2 + 1][1], cb[0], cb[1]);
                mma_f16(oacc[1][2 * np],
                        pf[1][2 * s2][0], pf[1][2 * s2][1],
                        pf[1][2 * s2 + 1][0], pf[1][2 * s2 + 1][1], cb[0], cb[1]);
                mma_f16(oacc[0][2 * np + 1],
                        pf[0][2 * s2][0], pf[0][2 * s2][1],
                        pf[0][2 * s2 + 1][0], pf[0][2 * s2 + 1][1], cb[2], cb[3]);
                mma_f16(oacc[1][2 * np + 1],
                        pf[1][2 * s2][0], pf[1][2 * s2][1],
                        pf[1][2 * s2 + 1][0], pf[1][2 * s2 + 1][1], cb[2], cb[3]);
                cb[0] = nb[0]; cb[1] = nb[1]; cb[2] = nb[2]; cb[3] = nb[3];
            }
        }
    }

    // ---- Epilogue: reduce psum over la3 quad, scale, write f32 ----
#pragma unroll
    for (int mt = 0; mt < 2; mt++) {
        float s0 = psum[mt][0], s1 = psum[mt][1];
        s0 += __shfl_xor_sync(0xffffffffu, s0, 1);
        s0 += __shfl_xor_sync(0xffffffffu, s0, 2);
        s1 += __shfl_xor_sync(0xffffffffu, s1, 1);
        s1 += __shfl_xor_sync(0xffffffffu, s1, 2);
        float sc0 = 8.0f / s0;
        float sc1 = 8.0f / s1;
        int rlo = q0 + wr + mt * 16 + g;
#pragma unroll
        for (int nt = 0; nt < 8; nt++) {
            int col = h * ND + 8 * nt + 2 * la3;
            float2 lo = make_float2(oacc[mt][nt][0] * sc0, oacc[mt][nt][1] * sc0);
            float2 hi = make_float2(oacc[mt][nt][2] * sc1, oacc[mt][nt][3] * sc1);
            *(float2*)(Out + (size_t)rlo * OUTF + col) = lo;
            *(float2*)(Out + (size_t)(rlo + 8) * OUTF + col) = hi;
        }
    }
}

// ===========================================================================
extern "C" void kernel_launch(void* const* d_in, const int* in_sizes, int n_in,
                              void* d_out, int out_size) {
    const float* x = (const float*)d_in[0];
    const float* W = (const float*)d_in[1];
    const float* mem = (const float*)d_in[2];
    float* out = (float*)d_out;

    uint32_t *xh, *wh, *qh, *mh;
    cudaGetSymbolAddress((void**)&xh, g_xh);
    cudaGetSymbolAddress((void**)&wh, g_wh);
    cudaGetSymbolAddress((void**)&qh, g_qh);
    cudaGetSymbolAddress((void**)&mh, g_mh);

    cudaFuncSetAttribute(qgemm_h, cudaFuncAttributeMaxDynamicSharedMemorySize,
                         QG_SMEM);
    cudaFuncSetAttribute(attn_h, cudaFuncAttributeMaxDynamicSharedMemorySize,
                         AT_SMEM);

    cvt_pack<<<(NB * INF / 4) / 256, 256>>>((const float4*)x, (uint2*)xh,
                                            NB * INF / 4);
    cvt_pack<<<(OUTF * INF / 4) / 256, 256>>>((const float4*)W, (uint2*)wh,
                                              OUTF * INF / 4);
    rownorm64_h<<<(NH * NM) / 8, 256>>>(mem, mh);
    qgemm_h<<<dim3(OUTF / 128, NB / 128), 256, QG_SMEM>>>(xh, wh, qh);
    attn_h<<<dim3(NB / 256, NH), 256, AT_SMEM>>>(qh, mh, out);
}

// round 17
// speedup vs baseline: 1.0513x; 1.0513x over previous
#include <cuda_runtime.h>
#include <cstdint>

#define NB 4096
#define INF 1024
#define OUTF 1024
#define NH 16
#define NM 4096
#define ND 64

// Scratch (device globals: allocation-free rule). All fp16-pair packed (u32).
__device__ uint32_t g_xh[NB * INF / 2];
__device__ uint32_t g_wh[OUTF * INF / 2];
__device__ uint32_t g_qh[NB * OUTF / 2];     // q-normalized * log2(e), fp16
__device__ uint32_t g_mh[NH * NM * ND / 2];  // normalized memories (K), fp16

// ===========================================================================
// helpers
// ===========================================================================
__device__ __forceinline__ uint32_t smem_u32(const void* p) {
    uint32_t a;
    asm("{ .reg .u64 t; cvta.to.shared.u64 t, %1; cvt.u32.u64 %0, t; }"
        : "=r"(a) : "l"(p));
    return a;
}
__device__ __forceinline__ uint32_t pack_h2(float lo, float hi) {
    uint32_t r;
    asm("cvt.rn.f16x2.f32 %0, %1, %2;" : "=r"(r) : "f"(hi), "f"(lo));
    return r;
}
__device__ __forceinline__ uint32_t ex2h2(uint32_t x) {
    uint32_t r;
    asm("ex2.approx.f16x2 %0, %1;" : "=r"(r) : "r"(x));
    return r;
}
__device__ __forceinline__ void mma_f16(float* d, uint32_t a0, uint32_t a1,
                                        uint32_t a2, uint32_t a3,
                                        uint32_t b0, uint32_t b1) {
    asm volatile(
        "mma.sync.aligned.m16n8k16.row.col.f32.f16.f16.f32 "
        "{%0,%1,%2,%3},{%4,%5,%6,%7},{%8,%9},{%0,%1,%2,%3};"
        : "+f"(d[0]), "+f"(d[1]), "+f"(d[2]), "+f"(d[3])
        : "r"(a0), "r"(a1), "r"(a2), "r"(a3), "r"(b0), "r"(b1));
}
__device__ __forceinline__ void ldmat_x4(uint32_t& r0, uint32_t& r1,
                                         uint32_t& r2, uint32_t& r3,
                                         uint32_t addr) {
    asm volatile("ldmatrix.sync.aligned.m8n8.x4.shared.b16 {%0,%1,%2,%3}, [%4];"
                 : "=r"(r0), "=r"(r1), "=r"(r2), "=r"(r3) : "r"(addr));
}
__device__ __forceinline__ void ldmat_x4_t(uint32_t& r0, uint32_t& r1,
                                           uint32_t& r2, uint32_t& r3,
                                           uint32_t addr) {
    asm volatile(
        "ldmatrix.sync.aligned.m8n8.x4.trans.shared.b16 {%0,%1,%2,%3}, [%4];"
        : "=r"(r0), "=r"(r1), "=r"(r2), "=r"(r3) : "r"(addr));
}
__device__ __forceinline__ void cpasync16(uint32_t dst, const void* src) {
    asm volatile("cp.async.cg.shared.global [%0], [%1], 16;"
                 :: "r"(dst), "l"(src) : "memory");
}
__device__ __forceinline__ void cp_commit() {
    asm volatile("cp.async.commit_group;" ::: "memory");
}

// ===========================================================================
// Pack f32 -> fp16 pairs
// ===========================================================================
__global__ __launch_bounds__(256) void cvt_pack(const float4* __restrict__ src,
                                                uint2* __restrict__ dst, int n4) {
    int i = blockIdx.x * 256 + threadIdx.x;
    if (i < n4) {
        float4 v = src[i];
        uint2 o;
        o.x = pack_h2(v.x, v.y);
        o.y = pack_h2(v.z, v.w);
        dst[i] = o;
    }
}

// ===========================================================================
// Row L2-normalize memories, 64-elem rows -> fp16 pairs
// ===========================================================================
__global__ __launch_bounds__(256) void rownorm64_h(const float* __restrict__ src,
                                                   uint32_t* __restrict__ dst) {
    int row = blockIdx.x * 8 + (threadIdx.x >> 5);
    int lane = threadIdx.x & 31;
    float2 v = *(const float2*)(src + (size_t)row * 64 + lane * 2);
    float ss = fmaf(v.x, v.x, v.y * v.y);
#pragma unroll
    for (int o = 16; o > 0; o >>= 1) ss += __shfl_xor_sync(0xffffffffu, ss, o);
    float r = rsqrtf(ss);
    dst[(size_t)row * 32 + lane] = pack_h2(v.x * r, v.y * r);
}

// ===========================================================================
// q-GEMM (fp16): qh = rownorm64(x @ W^T) * log2(e) -> fp16 pairs.
// 128x128 tile, BK=32, 3-stage cp.async, 256 thr, warp tile 32x64.
// A and B fragments via ldmatrix.x4 (48 LDS.32 -> 12 ldmatrix per k-iter).
// ===========================================================================
#define QGS 20
#define QG_TILE (128 * QGS)
#define QG_WOFF (3 * QG_TILE)
#define QG_SMEM (6 * QG_TILE * 4)

__global__ __launch_bounds__(256, 2) void qgemm_h(const uint32_t* __restrict__ Xh,
                                                  const uint32_t* __restrict__ Wh,
                                                  uint32_t* __restrict__ Qh) {
    extern __shared__ uint32_t qsm[];
    uint32_t smb = smem_u32(qsm);

    int tid = threadIdx.x;
    int lane = tid & 31, w = tid >> 5;
    int g = lane >> 2, la3 = lane & 3;
    int wm = (w & 3) * 32, wn = (w >> 2) * 64;
    int m0 = blockIdx.y * 128, n0 = blockIdx.x * 128;

    float acc[2][8][4];
#pragma unroll
    for (int mt = 0; mt < 2; mt++)
#pragma unroll
        for (int nt = 0; nt < 8; nt++)
#pragma unroll
            for (int e = 0; e < 4; e++) acc[mt][nt][e] = 0.f;

    int sr = tid >> 1, sc = (tid & 1) * 8;
#define QGH_STAGE(kt, sl)                                                      \
    do {                                                                       \
        _Pragma("unroll")                                                      \
        for (int v = 0; v < 2; v++) {                                          \
            cpasync16(smb + (uint32_t)((sl) * QG_TILE + sr * QGS + sc + 4 * v) * 4, \
                      Xh + (size_t)(m0 + sr) * (INF / 2) + (kt) * 16 + sc + 4 * v); \
            cpasync16(smb + (uint32_t)(QG_WOFF + (sl) * QG_TILE + sr * QGS + sc + 4 * v) * 4, \
                      Wh + (size_t)(n0 + sr) * (INF / 2) + (kt) * 16 + sc + 4 * v); \
        }                                                                      \
    } while (0)

    QGH_STAGE(0, 0); cp_commit();
    QGH_STAGE(1, 1); cp_commit();

    // ldmatrix lane->address offsets (word units, relative to tile base)
    int kgr = lane >> 3, ki = lane & 7;
    // A-frag map: a0 rows+0..7 col+0 | a1 rows+8..15 col+0
    //             a2 rows+0..7 col+4 | a3 rows+8..15 col+4
    uint32_t aoff =
        (uint32_t)((((kgr & 1) * 8) + ki) * QGS + (kgr >> 1) * 4) * 4;
    // B-frag map (two adjacent n8 tiles per x4):
    //   m0 rows+0..7 col+0 (b0 even) | m1 rows+0..7 col+4 (b1 even)
    //   m2 rows+8..15 col+0 (b0 odd) | m3 rows+8..15 col+4 (b1 odd)
    uint32_t boff =
        (uint32_t)((((kgr >> 1) * 8) + ki) * QGS + (kgr & 1) * 4) * 4;

    for (int kt = 0; kt < 32; kt++) {
        if (kt < 31) asm volatile("cp.async.wait_group 1;" ::: "memory");
        else         asm volatile("cp.async.wait_group 0;" ::: "memory");
        __syncthreads();
        if (kt + 2 < 32) { QGH_STAGE(kt + 2, (kt + 2) % 3); cp_commit(); }

        uint32_t xb = smb + (uint32_t)((kt % 3) * QG_TILE) * 4;
        uint32_t wb = smb + (uint32_t)(QG_WOFF + (kt % 3) * QG_TILE) * 4;

#pragma unroll
        for (int s = 0; s < 2; s++) {
            uint32_t af[2][4];
#pragma unroll
            for (int mt = 0; mt < 2; mt++)
                ldmat_x4(af[mt][0], af[mt][1], af[mt][2], af[mt][3],
                         xb + aoff +
                             (uint32_t)(((wm + mt * 16) * QGS + 8 * s) * 4));
#pragma unroll
            for (int j = 0; j < 4; j++) {
                uint32_t b0a, b1a, b0b, b1b;
                ldmat_x4(b0a, b1a, b0b, b1b,
                         wb + boff +
                             (uint32_t)(((wn + 16 * j) * QGS + 8 * s) * 4));
                mma_f16(acc[0][2 * j], af[0][0], af[0][1], af[0][2], af[0][3],
                        b0a, b1a);
                mma_f16(acc[1][2 * j], af[1][0], af[1][1], af[1][2], af[1][3],
                        b0a, b1a);
                mma_f16(acc[0][2 * j + 1], af[0][0], af[0][1], af[0][2],
                        af[0][3], b0b, b1b);
                mma_f16(acc[1][2 * j + 1], af[1][0], af[1][1], af[1][2],
                        af[1][3], b0b, b1b);
            }
        }
    }

    // fused per-head (64-col) L2 norm epilogue, scaled by log2(e); fp16 out
#pragma unroll
    for (int mt = 0; mt < 2; mt++) {
        float sq0 = 0.f, sq1 = 0.f;
#pragma unroll
        for (int nt = 0; nt < 8; nt++) {
            sq0 = fmaf(acc[mt][nt][0], acc[mt][nt][0], sq0);
            sq0 = fmaf(acc[mt][nt][1], acc[mt][nt][1], sq0);
            sq1 = fmaf(acc[mt][nt][2], acc[mt][nt][2], sq1);
            sq1 = fmaf(acc[mt][nt][3], acc[mt][nt][3], sq1);
        }
        sq0 += __shfl_xor_sync(0xffffffffu, sq0, 1);
        sq0 += __shfl_xor_sync(0xffffffffu, sq0, 2);
        sq1 += __shfl_xor_sync(0xffffffffu, sq1, 1);
        sq1 += __shfl_xor_sync(0xffffffffu, sq1, 2);
        float r0 = rsqrtf(sq0) * 1.44269504f;
        float r1 = rsqrtf(sq1) * 1.44269504f;
        int rlo = m0 + wm + mt * 16 + g;
#pragma unroll
        for (int nt = 0; nt < 8; nt++) {
            int colw = (n0 + wn + nt * 8) / 2 + la3;
            Qh[(size_t)rlo * (OUTF / 2) + colw] =
                pack_h2(acc[mt][nt][0] * r0, acc[mt][nt][1] * r0);
            Qh[(size_t)(rlo + 8) * (OUTF / 2) + colw] =
                pack_h2(acc[mt][nt][2] * r1, acc[mt][nt][3] * r1);
        }
    }
}

// ===========================================================================
// Attention (exact R15 config = best 237.7us): CTA = (head, 256 q rows),
// 8 warps x 32 rows. 3-slot cp.async K pipeline, one __syncthreads per tile.
// GEMM1: persistent Q a-frags, pipelined non-trans ldmatrix B. ex2.f16x2 P.
// GEMM2: pipelined trans-ldmatrix B; row sums via constant ones b-frag MMA.
// smem (u32 words): K[3][64*36] | Qstage[256*36]   (64.5 KB)
// ===========================================================================
#define KS 36
#define KTW (64 * KS)
#define QST_OFF (3 * KTW)
#define QS 36
#define AT_SMEM ((QST_OFF + 256 * QS) * 4)
#define NTILES (NM / 64)

__global__ __launch_bounds__(256, 1) void attn_h(const uint32_t* __restrict__ Qh,
                                                 const uint32_t* __restrict__ Mh,
                                                 float* __restrict__ Out) {
    extern __shared__ uint32_t smu[];
    uint32_t smb = smem_u32(smu);

    int tid = threadIdx.x;
    int lane = tid & 31, w = tid >> 5;
    int g = lane >> 2, la3 = lane & 3;
    int h = blockIdx.y;
    int q0 = blockIdx.x * 256;
    const uint32_t* mhw = Mh + (size_t)h * NM * (ND / 2);

    // ---- Q stage (cp.async group): 256 rows x 32 words ----
    {
        const uint32_t* qp = Qh + (size_t)(q0 + tid) * (OUTF / 2) + h * 32;
#pragma unroll
        for (int u = 0; u < 8; u++)
            cpasync16(smb + (uint32_t)(QST_OFF + tid * QS + u * 4) * 4, qp + u * 4);
        cp_commit();
    }

#define ATH_STAGE(tt, sl)                                                      \
    do {                                                                       \
        _Pragma("unroll")                                                      \
        for (int u = 0; u < 2; u++) {                                          \
            int chunk = tid + 256 * u;                                         \
            int r = chunk >> 3, cq = (chunk & 7) * 4;                          \
            cpasync16(smb + (uint32_t)((sl) * KTW + r * KS + cq) * 4,          \
                      mhw + (size_t)((tt) * 64 + r) * 32 + cq);                \
        }                                                                      \
    } while (0)

    ATH_STAGE(0, 0); cp_commit();
    ATH_STAGE(1, 1); cp_commit();

    asm volatile("cp.async.wait_group 2;" ::: "memory");  // Q complete
    __syncthreads();

    // ---- persistent Q a-frags (fp16: 4 k16 slices, 2 m16 tiles) ----
    int wr = w * 32;
    uint32_t qf[2][4][4];
    {
        const uint32_t* qb = smu + QST_OFF;
#pragma unroll
        for (int mt = 0; mt < 2; mt++)
#pragma unroll
            for (int s = 0; s < 4; s++) {
                int rr = wr + mt * 16 + g;
                qf[mt][s][0] = qb[rr * QS + 8 * s + la3];
                qf[mt][s][1] = qb[(rr + 8) * QS + 8 * s + la3];
                qf[mt][s][2] = qb[rr * QS + 8 * s + la3 + 4];
                qf[mt][s][3] = qb[(rr + 8) * QS + 8 * s + la3 + 4];
            }
    }

    // ---- GEMM1 non-trans ldmatrix per-lane offset ----
    int kgr = lane >> 3, ki = lane & 7;
    uint32_t koff =
        (uint32_t)(((kgr >> 1) * 8 + ki) * KS + (kgr & 1) * 4) * 4;

    // ---- GEMM2 trans-ldmatrix per-lane offset ----
    int vrow = ((lane >> 3) & 1) * 8 + (lane & 7);
    int vcolw = (lane >> 4) * 4;
    uint32_t voff = (uint32_t)(vrow * KS + vcolw) * 4;

    // constant ones b-frag (column n=0 of an all-ones-column matrix)
    uint32_t bone = (g == 0) ? 0x3C003C00u : 0u;

    float oacc[2][8][4];
#pragma unroll
    for (int mt = 0; mt < 2; mt++)
#pragma unroll
        for (int nt = 0; nt < 8; nt++)
#pragma unroll
            for (int e = 0; e < 4; e++) oacc[mt][nt][e] = 0.f;
    float oext[2][4];
#pragma unroll
    for (int mt = 0; mt < 2; mt++)
#pragma unroll
        for (int e = 0; e < 4; e++) oext[mt][e] = 0.f;

    for (int t = 0; t < NTILES; t++) {
        if (t < NTILES - 1) asm volatile("cp.async.wait_group 1;" ::: "memory");
        else                asm volatile("cp.async.wait_group 0;" ::: "memory");
        __syncthreads();  // K(t) visible; all warps done with slot (t-1)%3

        // stage t+2 into slot (t+2)%3 = (t-1)%3 (freed by the sync above)
        if (t + 2 < NTILES) { ATH_STAGE(t + 2, (t + 2) % 3); cp_commit(); }

        uint32_t slotb = smb + (uint32_t)((t % 3) * KTW) * 4;
        uint32_t kbase = slotb + koff;
        uint32_t vbase = slotb + voff;

        // ---- GEMM1: S = Q K^T, B loads pipelined one step ahead ----
        float sacc[2][8][4];
#pragma unroll
        for (int mt = 0; mt < 2; mt++)
#pragma unroll
            for (int nt = 0; nt < 8; nt++)
#pragma unroll
                for (int e = 0; e < 4; e++) sacc[mt][nt][e] = 0.f;

        {
            uint32_t cb[4];  // current b-frags
            ldmat_x4(cb[0], cb[1], cb[2], cb[3], kbase);  // (s=0,j=0)
#pragma unroll
            for (int it = 0; it < 16; it++) {
                int s = it >> 2, j = it & 3;
                uint32_t nb[4];
                if (it < 15) {
                    int n_it = it + 1;
                    int ns = n_it >> 2, nj = n_it & 3;
                    ldmat_x4(nb[0], nb[1], nb[2], nb[3],
                             kbase + (uint32_t)((16 * nj * KS + 8 * ns) * 4));
                }
                mma_f16(sacc[0][2 * j], qf[0][s][0], qf[0][s][1], qf[0][s][2],
                        qf[0][s][3], cb[0], cb[1]);
                mma_f16(sacc[1][2 * j], qf[1][s][0], qf[1][s][1], qf[1][s][2],
                        qf[1][s][3], cb[0], cb[1]);
                mma_f16(sacc[0][2 * j + 1], qf[0][s][0], qf[0][s][1],
                        qf[0][s][2], qf[0][s][3], cb[2], cb[3]);
                mma_f16(sacc[1][2 * j + 1], qf[1][s][0], qf[1][s][1],
                        qf[1][s][2], qf[1][s][3], cb[2], cb[3]);
                cb[0] = nb[0]; cb[1] = nb[1]; cb[2] = nb[2]; cb[3] = nb[3];
            }
        }

        // ---- P = 2^S via ex2.approx.f16x2 -> fp16 a-frags directly ----
        uint32_t pf[2][8][2];
#pragma unroll
        for (int mt = 0; mt < 2; mt++)
#pragma unroll
            for (int nt = 0; nt < 8; nt++) {
                pf[mt][nt][0] = ex2h2(pack_h2(sacc[mt][nt][0], sacc[mt][nt][1]));
                pf[mt][nt][1] = ex2h2(pack_h2(sacc[mt][nt][2], sacc[mt][nt][3]));
            }

        // ---- GEMM2: O += P V, B loads pipelined one step ahead ----
        {
            uint32_t cb[4];
            ldmat_x4_t(cb[0], cb[1], cb[2], cb[3], vbase);  // (s2=0,np=0)
#pragma unroll
            for (int it = 0; it < 16; it++) {
                int s2 = it >> 2, np = it & 3;
                uint32_t nb[4];
                if (it < 15) {
                    int n_it = it + 1;
                    int ns2 = n_it >> 2, nnp = n_it & 3;
                    ldmat_x4_t(nb[0], nb[1], nb[2], nb[3],
                               vbase + (uint32_t)(16 * ns2 * KS) * 4 +
                                   (uint32_t)(nnp * 32));
                }
                mma_f16(oacc[0][2 * np],
                        pf[0][2 * s2][0], pf[0][2 * s2][1],
                        pf[0][2 * s2 + 1][0], pf[0][2 * s2 + 1][1], cb[0], cb[1]);
                mma_f16(oacc[1][2 * np],
                        pf[1][2 * s2][0], pf[1][2 * s2][1],
                        pf[1][2 * s2 + 1][0], pf[1][2 * s2 + 1][1], cb[0], cb[1]);
                mma_f16(oacc[0][2 * np + 1],
                        pf[0][2 * s2][0], pf[0][2 * s2][1],
                        pf[0][2 * s2 + 1][0], pf[0][2 * s2 + 1][1], cb[2], cb[3]);
                mma_f16(oacc[1][2 * np + 1],
                        pf[1][2 * s2][0], pf[1][2 * s2][1],
                        pf[1][2 * s2 + 1][0], pf[1][2 * s2 + 1][1], cb[2], cb[3]);
                if (np == 3) {  // ones row-sum MMA for this s2 (no load)
                    mma_f16(oext[0],
                            pf[0][2 * s2][0], pf[0][2 * s2][1],
                            pf[0][2 * s2 + 1][0], pf[0][2 * s2 + 1][1],
                            bone, bone);
                    mma_f16(oext[1],
                            pf[1][2 * s2][0], pf[1][2 * s2][1],
                            pf[1][2 * s2 + 1][0], pf[1][2 * s2 + 1][1],
                            bone, bone);
                }
                cb[0] = nb[0]; cb[1] = nb[1]; cb[2] = nb[2]; cb[3] = nb[3];
            }
        }
    }

    // ---- Epilogue: scale by sqrt(64)/rowsum, write out f32 ----
#pragma unroll
    for (int mt = 0; mt < 2; mt++) {
        // row sums live in la3==0 lanes (ones column = local col 0)
        float s0 = __shfl_sync(0xffffffffu, oext[mt][0], lane & 28);
        float s1 = __shfl_sync(0xffffffffu, oext[mt][2], lane & 28);
        float sc0 = 8.0f / s0;
        float sc1 = 8.0f / s1;
        int rlo = q0 + wr + mt * 16 + g;
#pragma unroll
        for (int nt = 0; nt < 8; nt++) {
            int col = h * ND + 8 * nt + 2 * la3;
            float2 lo = make_float2(oacc[mt][nt][0] * sc0, oacc[mt][nt][1] * sc0);
            float2 hi = make_float2(oacc[mt][nt][2] * sc1, oacc[mt][nt][3] * sc1);
            *(float2*)(Out + (size_t)rlo * OUTF + col) = lo;
            *(float2*)(Out + (size_t)(rlo + 8) * OUTF + col) = hi;
        }
    }
}

// ===========================================================================
extern "C" void kernel_launch(void* const* d_in, const int* in_sizes, int n_in,
                              void* d_out, int out_size) {
    const float* x = (const float*)d_in[0];
    const float* W = (const float*)d_in[1];
    const float* mem = (const float*)d_in[2];
    float* out = (float*)d_out;

    uint32_t *xh, *wh, *qh, *mh;
    cudaGetSymbolAddress((void**)&xh, g_xh);
    cudaGetSymbolAddress((void**)&wh, g_wh);
    cudaGetSymbolAddress((void**)&qh, g_qh);
    cudaGetSymbolAddress((void**)&mh, g_mh);

    cudaFuncSetAttribute(qgemm_h, cudaFuncAttributeMaxDynamicSharedMemorySize,
                         QG_SMEM);
    cudaFuncSetAttribute(attn_h, cudaFuncAttributeMaxDynamicSharedMemorySize,
                         AT_SMEM);

    cvt_pack<<<(NB * INF / 4) / 256, 256>>>((const float4*)x, (uint2*)xh,
                                            NB * INF / 4);
    cvt_pack<<<(OUTF * INF / 4) / 256, 256>>>((const float4*)W, (uint2*)wh,
                                              OUTF * INF / 4);
    rownorm64_h<<<(NH * NM) / 8, 256>>>(mem, mh);
    qgemm_h<<<dim3(OUTF / 128, NB / 128), 256, QG_SMEM>>>(xh, wh, qh);
    attn_h<<<dim3(NB / 256, NH), 256, AT_SMEM>>>(qh, mh, out);
}